// round 3
// baseline (speedup 1.0000x reference)
#include <cuda_runtime.h>
#include <cuda_fp16.h>
#include <cstdint>

#define N_ITEMS_K 1000000
#define FEAT_K    256
#define BAG_K     128
#define N_BAGS_K  50000
#define TILE_K    128
#define N_TILES_K ((N_ITEMS_K + TILE_K - 1) / TILE_K)   // 7813
#define EPS_K     1e-5f

// ---------------- device scratch (no allocations allowed) ----------------
// [0, N_BAGS*BAG)       : segment sums
// [N_BAGS*BAG, +BAG)    : column sum of bag means
// [N_BAGS*BAG+BAG,+BAG) : column sum of squares
__device__ float g_scratch[(size_t)N_BAGS_K * BAG_K + 2 * BAG_K];

// ---------------- shared memory layout (byte offsets) ----------------
// seg ids   : [0, 512)
// b vector  : [512, 1024)
// W_hi fp16 : [1024, 66560)        128 rows x 512 B, 16B-unit XOR swizzle
// W_lo fp16 : [66560, 132096)
// x buffers : [132096, 197632)     2 bufs x (hi 16 KB + lo 16 KB)
// h (alias) : [132096, 199680)     128 x 132 f32
#define SM_SEG   0
#define SM_B     512
#define SM_WHI   1024
#define SM_WLO   66560
#define SM_X     132096
#define XBUF(b,hl) (SM_X + (b) * 32768 + (hl) * 16384)
#define SM_H     SM_X
#define H_STRIDE 132
#define SMEM_DYN 200704

__device__ __forceinline__ uint32_t smem_u32(const void* p) {
    uint32_t a;
    asm("{ .reg .u64 t; cvta.to.shared.u64 t, %1; cvt.u32.u64 %0, t; }" : "=r"(a) : "l"(p));
    return a;
}

__device__ __forceinline__ void ldsm4(uint32_t* r, uint32_t addr) {
    asm volatile("ldmatrix.sync.aligned.m8n8.x4.shared.b16 {%0,%1,%2,%3}, [%4];"
                 : "=r"(r[0]), "=r"(r[1]), "=r"(r[2]), "=r"(r[3]) : "r"(addr));
}

__device__ __forceinline__ void mma16816(float* c, const uint32_t* a,
                                         uint32_t b0, uint32_t b1) {
    asm volatile(
        "mma.sync.aligned.m16n8k16.row.col.f32.f16.f16.f32 "
        "{%0,%1,%2,%3},{%4,%5,%6,%7},{%8,%9},{%0,%1,%2,%3};"
        : "+f"(c[0]), "+f"(c[1]), "+f"(c[2]), "+f"(c[3])
        : "r"(a[0]), "r"(a[1]), "r"(a[2]), "r"(a[3]), "r"(b0), "r"(b1));
}

// split one float into fp16 hi + fp16 residual
__device__ __forceinline__ void split2(float x, float y, uint32_t& hi, uint32_t& lo) {
    __half2 h, l;
    h.x = __float2half_rn(x);
    h.y = __float2half_rn(y);
    l.x = __float2half_rn(x - __half2float(h.x));
    l.y = __float2half_rn(y - __half2float(h.y));
    hi = *(uint32_t*)&h;
    lo = *(uint32_t*)&l;
}

// STS one float4 (4 feats) of row `row`, f4-slot `f4` into buffer nb (hi+lo)
__device__ __forceinline__ void sts_f4(char* sm, int nb, int row, int f4, float4 v) {
    uint32_t hi0, lo0, hi1, lo1;
    split2(v.x, v.y, hi0, lo0);
    split2(v.z, v.w, hi1, lo1);
    uint32_t off = (uint32_t)row * 128u
                 + ((uint32_t)((f4 >> 1) ^ (row & 7)) << 4)
                 + (uint32_t)(f4 & 1) * 8u;
    *(uint32_t*)(sm + XBUF(nb, 0) + off)     = hi0;
    *(uint32_t*)(sm + XBUF(nb, 0) + off + 4) = hi1;
    *(uint32_t*)(sm + XBUF(nb, 1) + off)     = lo0;
    *(uint32_t*)(sm + XBUF(nb, 1) + off + 4) = lo1;
}

__global__ void __launch_bounds__(128, 1)
fused_gemm_seg_kernel(const float* __restrict__ x, const float* __restrict__ W,
                      const float* __restrict__ bvec, const int* __restrict__ seg)
{
    extern __shared__ char sm[];
    const uint32_t sb = smem_u32(sm);
    const int tid  = threadIdx.x;
    const int lane = tid & 31;
    const int wid  = tid >> 5;

    int*   seg_s = (int*)(sm + SM_SEG);
    float* b_s   = (float*)(sm + SM_B);
    float* h_s   = (float*)(sm + SM_H);

    // ---- one-time: W -> fp16 hi/lo, swizzled [n][512B] ----
    for (int idx = tid; idx < BAG_K * FEAT_K; idx += 128) {
        int n = idx >> 8, k = idx & 255;
        float v = W[idx];
        __half hv = __float2half_rn(v);
        __half lv = __float2half_rn(v - __half2float(hv));
        uint32_t off = (uint32_t)n * 512u
                     + ((uint32_t)((k >> 3) ^ (n & 7)) << 4)
                     + (uint32_t)(k & 7) * 2u;
        *(__half*)(sm + SM_WHI + off) = hv;
        *(__half*)(sm + SM_WLO + off) = lv;
    }
    if (tid < BAG_K) b_s[tid] = bvec[tid];

    // ldmatrix lane geometry
    const int a_row_in = ((lane >> 3) & 1) * 8 + (lane & 7);   // row within m16 tile
    const int a_ku     = lane >> 4;                            // k-unit select
    const int b_ln     = ((lane >> 4) << 3) + (lane & 7);      // n within 16-wide pair
    const int b_ku     = (lane >> 3) & 1;

    const uint32_t a_off_m0 = (uint32_t)(wid * 32 + a_row_in) * 128u;
    const uint32_t a_off_m1 = a_off_m0 + 16u * 128u;
    const uint32_t b_base   = (uint32_t)b_ln * 512u;
    const uint32_t lane7    = (uint32_t)(lane & 7);

    const float4* xf4 = (const float4*)x;

    for (int t = blockIdx.x; t < N_TILES_K; t += gridDim.x) {
        const int i0 = t * TILE_K;
        const int rows = min(TILE_K, N_ITEMS_K - i0);
        if (tid < rows) seg_s[tid] = seg[i0 + tid];

        float acc[2][16][4];
        #pragma unroll
        for (int m = 0; m < 2; m++)
            #pragma unroll
            for (int nt = 0; nt < 16; nt++)
                #pragma unroll
                for (int i = 0; i < 4; i++) acc[m][nt][i] = 0.f;

        // ---- quarter 0 -> buffer 0 ----
        #pragma unroll
        for (int it = 0; it < 16; it++) {
            int g = it * 128 + tid;
            int row = g >> 4, f4 = g & 15;
            float4 v = (i0 + row < N_ITEMS_K)
                     ? xf4[(size_t)(i0 + row) * 64 + f4]
                     : make_float4(0.f, 0.f, 0.f, 0.f);
            sts_f4(sm, 0, row, f4, v);
        }
        __syncthreads();

        int cur = 0;
        #pragma unroll
        for (int q = 0; q < 4; q++) {
            float4 pv[4];
            int prow[4], pf4[4];
            #pragma unroll
            for (int sl = 0; sl < 4; sl++) {
                // prefetch next quarter (group sl) while mma below runs
                float4 nv[4];
                int nrow[4], nf4[4];
                if (q < 3) {
                    #pragma unroll
                    for (int gi = 0; gi < 4; gi++) {
                        int g = (sl * 4 + gi) * 128 + tid;
                        nrow[gi] = g >> 4;
                        nf4[gi]  = g & 15;
                        nv[gi] = (i0 + nrow[gi] < N_ITEMS_K)
                               ? xf4[(size_t)(i0 + nrow[gi]) * 64 + (q + 1) * 16 + nf4[gi]]
                               : make_float4(0.f, 0.f, 0.f, 0.f);
                    }
                }

                // A fragments (hi and lo) for this k-step
                uint32_t Ah0[4], Ah1[4], Al0[4], Al1[4];
                uint32_t aun = ((uint32_t)(2 * sl + a_ku) ^ lane7) << 4;
                ldsm4(Ah0, sb + XBUF(cur, 0) + a_off_m0 + aun);
                ldsm4(Ah1, sb + XBUF(cur, 0) + a_off_m1 + aun);
                ldsm4(Al0, sb + XBUF(cur, 1) + a_off_m0 + aun);
                ldsm4(Al1, sb + XBUF(cur, 1) + a_off_m1 + aun);

                const int sg = q * 4 + sl;
                const uint32_t bun = ((uint32_t)(2 * sg + b_ku) ^ lane7) << 4;
                #pragma unroll
                for (int j = 0; j < 8; j++) {
                    uint32_t boff = b_base + (uint32_t)j * 8192u + bun;
                    uint32_t Bh[4], Bl[4];
                    ldsm4(Bh, sb + SM_WHI + boff);
                    ldsm4(Bl, sb + SM_WLO + boff);
                    // x_hi*W_hi
                    mma16816(acc[0][2*j],   Ah0, Bh[0], Bh[1]);
                    mma16816(acc[0][2*j+1], Ah0, Bh[2], Bh[3]);
                    mma16816(acc[1][2*j],   Ah1, Bh[0], Bh[1]);
                    mma16816(acc[1][2*j+1], Ah1, Bh[2], Bh[3]);
                    // x_hi*W_lo
                    mma16816(acc[0][2*j],   Ah0, Bl[0], Bl[1]);
                    mma16816(acc[0][2*j+1], Ah0, Bl[2], Bl[3]);
                    mma16816(acc[1][2*j],   Ah1, Bl[0], Bl[1]);
                    mma16816(acc[1][2*j+1], Ah1, Bl[2], Bl[3]);
                    // x_lo*W_hi
                    mma16816(acc[0][2*j],   Al0, Bh[0], Bh[1]);
                    mma16816(acc[0][2*j+1], Al0, Bh[2], Bh[3]);
                    mma16816(acc[1][2*j],   Al1, Bh[0], Bh[1]);
                    mma16816(acc[1][2*j+1], Al1, Bh[2], Bh[3]);
                }

                if (q < 3) {
                    if (sl > 0) {
                        #pragma unroll
                        for (int gi = 0; gi < 4; gi++)
                            sts_f4(sm, cur ^ 1, prow[gi], pf4[gi], pv[gi]);
                    }
                    #pragma unroll
                    for (int gi = 0; gi < 4; gi++) {
                        pv[gi] = nv[gi]; prow[gi] = nrow[gi]; pf4[gi] = nf4[gi];
                    }
                }
            }
            if (q < 3) {
                #pragma unroll
                for (int gi = 0; gi < 4; gi++)
                    sts_f4(sm, cur ^ 1, prow[gi], pf4[gi], pv[gi]);
            }
            __syncthreads();
            cur ^= 1;
        }

        // ---- epilogue: +b, relu, write h (padded) ----
        {
            const int g2 = lane >> 2, t2 = lane & 3;
            #pragma unroll
            for (int m = 0; m < 2; m++) {
                const int r0 = wid * 32 + m * 16 + g2;
                #pragma unroll
                for (int nt = 0; nt < 16; nt++) {
                    const int c = nt * 8 + t2 * 2;
                    const float b0 = b_s[c], b1 = b_s[c + 1];
                    float2 v0, v1;
                    v0.x = fmaxf(acc[m][nt][0] + b0, 0.f);
                    v0.y = fmaxf(acc[m][nt][1] + b1, 0.f);
                    v1.x = fmaxf(acc[m][nt][2] + b0, 0.f);
                    v1.y = fmaxf(acc[m][nt][3] + b1, 0.f);
                    *(float2*)&h_s[(size_t)r0 * H_STRIDE + c]       = v0;
                    *(float2*)&h_s[(size_t)(r0 + 8) * H_STRIDE + c] = v1;
                }
            }
        }
        __syncthreads();

        // ---- segment reduce: thread = column; rows sorted by seg id ----
        {
            float a = 0.f;
            int cur_s = seg_s[0];
            for (int r = 0; r < rows; r++) {
                int s = seg_s[r];
                if (s != cur_s) {
                    atomicAdd(&g_scratch[(size_t)cur_s * BAG_K + tid], a);
                    a = 0.f;
                    cur_s = s;
                }
                a += h_s[r * H_STRIDE + tid];
            }
            atomicAdd(&g_scratch[(size_t)cur_s * BAG_K + tid], a);
        }
        __syncthreads();
    }
}

// ---- per-column batch stats over the 50k bag means ----
__global__ void __launch_bounds__(128) stats_kernel(const int* __restrict__ blen)
{
    const int c = threadIdx.x;
    float s = 0.f, ss = 0.f;
    for (int r = blockIdx.x; r < N_BAGS_K; r += gridDim.x) {
        float cnt = (float)max(blen[r], 1);
        float v = g_scratch[(size_t)r * BAG_K + c] / cnt;
        s += v;
        ss += v * v;
    }
    atomicAdd(&g_scratch[(size_t)N_BAGS_K * BAG_K + c], s);
    atomicAdd(&g_scratch[(size_t)N_BAGS_K * BAG_K + BAG_K + c], ss);
}

// ---- normalize ----
__global__ void __launch_bounds__(128) norm_kernel(const int* __restrict__ blen,
                                                   const float* __restrict__ gamma,
                                                   const float* __restrict__ beta,
                                                   float* __restrict__ out)
{
    const int c = threadIdx.x;
    const float inv_n = 1.f / (float)N_BAGS_K;
    float mean = g_scratch[(size_t)N_BAGS_K * BAG_K + c] * inv_n;
    float ex2  = g_scratch[(size_t)N_BAGS_K * BAG_K + BAG_K + c] * inv_n;
    float scale = rsqrtf(ex2 - mean * mean + EPS_K) * gamma[c];
    float shift = beta[c];
    for (int r = blockIdx.x; r < N_BAGS_K; r += gridDim.x) {
        float cnt = (float)max(blen[r], 1);
        float v = g_scratch[(size_t)r * BAG_K + c] / cnt;
        out[(size_t)r * BAG_K + c] = (v - mean) * scale + shift;
    }
}

extern "C" void kernel_launch(void* const* d_in, const int* in_sizes, int n_in,
                              void* d_out, int out_size)
{
    const float* x     = (const float*)d_in[0];
    const float* W     = (const float*)d_in[1];
    const float* bvec  = (const float*)d_in[2];
    const float* gamma = (const float*)d_in[3];
    const float* beta  = (const float*)d_in[4];
    const int*   seg   = (const int*)d_in[5];
    const int*   blen  = (const int*)d_in[6];
    float*       out   = (float*)d_out;

    (void)in_sizes; (void)n_in; (void)out_size;

    void* scratch = nullptr;
    cudaGetSymbolAddress(&scratch, g_scratch);
    cudaMemsetAsync(scratch, 0,
                    sizeof(float) * ((size_t)N_BAGS_K * BAG_K + 2 * BAG_K), 0);

    int dev = 0, nsm = 148;
    cudaGetDevice(&dev);
    cudaDeviceGetAttribute(&nsm, cudaDevAttrMultiProcessorCount, dev);

    cudaFuncSetAttribute(fused_gemm_seg_kernel,
                         cudaFuncAttributeMaxDynamicSharedMemorySize, SMEM_DYN);
    fused_gemm_seg_kernel<<<nsm, 128, SMEM_DYN>>>(x, W, bvec, seg);
    stats_kernel<<<500, 128>>>(blen);
    norm_kernel<<<2048, 128>>>(blen, gamma, beta, out);
}

// round 4
// speedup vs baseline: 1.6029x; 1.6029x over previous
#include <cuda_runtime.h>
#include <cuda_fp16.h>
#include <cstdint>

#define N_ITEMS_K 1000000
#define FEAT_K    256
#define BAG_K     128
#define N_BAGS_K  50000
#define TILE_K    128
#define N_TILES_K ((N_ITEMS_K + TILE_K - 1) / TILE_K)   // 7813
#define EPS_K     1e-5f

// ---------------- device scratch ----------------
// [0, N_BAGS*BAG)       : segment sums
// [N_BAGS*BAG, +BAG)    : column sum of bag means
// [N_BAGS*BAG+BAG,+BAG) : column sum of squares
__device__ float g_scratch[(size_t)N_BAGS_K * BAG_K + 2 * BAG_K];

// ---------------- shared memory layout (byte offsets) ----------------
// seg ids   : [0, 512)
// b vector  : [512, 1024)
// W_hi fp16 : [1024, 66560)      128 rows x 512 B, 16B-unit XOR swizzle
// W_lo fp16 : [66560, 132096)
// x bufs    : [132096, +2x32768) raw fp32 quarters, slot-XOR swizzle
// h (alias) : [132096, +67584)   128 x 132 f32
#define SM_SEG   0
#define SM_B     512
#define SM_WHI   1024
#define SM_WLO   66560
#define SM_X     132096
#define XBUF(b)  (SM_X + (b) * 32768)
#define SM_H     SM_X
#define H_STRIDE 132
#define SMEM_DYN (SM_X + TILE_K * H_STRIDE * 4)   // 199680

__device__ __forceinline__ uint32_t smem_u32(const void* p) {
    uint32_t a;
    asm("{ .reg .u64 t; cvta.to.shared.u64 t, %1; cvt.u32.u64 %0, t; }" : "=r"(a) : "l"(p));
    return a;
}

__device__ __forceinline__ void ldsm4(uint32_t* r, uint32_t addr) {
    asm volatile("ldmatrix.sync.aligned.m8n8.x4.shared.b16 {%0,%1,%2,%3}, [%4];"
                 : "=r"(r[0]), "=r"(r[1]), "=r"(r[2]), "=r"(r[3]) : "r"(addr));
}

__device__ __forceinline__ void mma16816(float* c, const uint32_t* a,
                                         uint32_t b0, uint32_t b1) {
    asm volatile(
        "mma.sync.aligned.m16n8k16.row.col.f32.f16.f16.f32 "
        "{%0,%1,%2,%3},{%4,%5,%6,%7},{%8,%9},{%0,%1,%2,%3};"
        : "+f"(c[0]), "+f"(c[1]), "+f"(c[2]), "+f"(c[3])
        : "r"(a[0]), "r"(a[1]), "r"(a[2]), "r"(a[3]), "r"(b0), "r"(b1));
}

__device__ __forceinline__ void cp_async16(uint32_t dst, const void* src, bool pred) {
    int sz = pred ? 16 : 0;
    asm volatile("cp.async.cg.shared.global [%0], [%1], 16, %2;"
                 :: "r"(dst), "l"(src), "r"(sz) : "memory");
}
#define CP_COMMIT() asm volatile("cp.async.commit_group;" ::: "memory")
#define CP_WAIT1()  asm volatile("cp.async.wait_group 1;" ::: "memory")
#define CP_WAIT0()  asm volatile("cp.async.wait_group 0;" ::: "memory")

// split two floats -> packed fp16 hi pair + fp16 residual pair
__device__ __forceinline__ void split2(float x, float y, uint32_t& hi, uint32_t& lo) {
    __half2 h, l;
    h.x = __float2half_rn(x);
    h.y = __float2half_rn(y);
    l.x = __float2half_rn(x - __half2float(h.x));
    l.y = __float2half_rn(y - __half2float(h.y));
    hi = *(uint32_t*)&h;
    lo = *(uint32_t*)&l;
}

__global__ void __launch_bounds__(256, 1)
fused_gemm_seg_kernel(const float* __restrict__ x, const float* __restrict__ W,
                      const float* __restrict__ bvec, const int* __restrict__ seg)
{
    extern __shared__ char sm[];
    const uint32_t sb = smem_u32(sm);
    const int tid  = threadIdx.x;
    const int lane = tid & 31;
    const int wid  = tid >> 5;

    int*   seg_s = (int*)(sm + SM_SEG);
    float* b_s   = (float*)(sm + SM_B);
    float* h_s   = (float*)(sm + SM_H);

    // ---- one-time: W -> fp16 hi/lo, swizzled [n][512B] ----
    for (int idx = tid; idx < BAG_K * FEAT_K; idx += 256) {
        int n = idx >> 8, k = idx & 255;
        float v = W[idx];
        __half hv = __float2half_rn(v);
        __half lv = __float2half_rn(v - __half2float(hv));
        uint32_t off = (uint32_t)n * 512u
                     + ((uint32_t)((k >> 3) ^ (n & 7)) << 4)
                     + (uint32_t)(k & 7) * 2u;
        *(__half*)(sm + SM_WHI + off) = hv;
        *(__half*)(sm + SM_WLO + off) = lv;
    }
    if (tid < BAG_K) b_s[tid] = bvec[tid];
    __syncthreads();

    // fragment lane geometry
    const int g  = lane >> 2;          // A/C row group within m16
    const int tq = lane & 3;           // k-pair / col-pair select
    const int b_ln = ((lane >> 4) << 3) + (lane & 7);
    const int b_ku = (lane >> 3) & 1;
    const uint32_t b_base = (uint32_t)b_ln * 512u;
    const uint32_t lane7  = (uint32_t)(lane & 7);

    const int R  = wid * 16 + g;       // this thread's upper A row
    const float4* xf4 = (const float4*)x;

    // x smem address for (row, k-local within 64-feat quarter)
    auto xoff = [&](int buf, int r, int kl) -> uint32_t {
        uint32_t s = (uint32_t)(kl >> 2);
        return (uint32_t)XBUF(buf) + (uint32_t)r * 256u
             + ((s ^ (((uint32_t)r & 7u) << 1)) << 4)
             + (uint32_t)(kl & 3) * 4u;
    };

    for (int t = blockIdx.x; t < N_TILES_K; t += gridDim.x) {
        const int i0 = t * TILE_K;
        const int rows = min(TILE_K, N_ITEMS_K - i0);
        if (tid < rows) seg_s[tid] = seg[i0 + tid];

        float acc[16][4];
        #pragma unroll
        for (int nt = 0; nt < 16; nt++)
            #pragma unroll
            for (int i = 0; i < 4; i++) acc[nt][i] = 0.f;

        // ---- prologue: cp.async quarters 0 and 1 ----
        #pragma unroll
        for (int q = 0; q < 2; q++) {
            #pragma unroll
            for (int it = 0; it < 8; it++) {
                int gg = it * 256 + tid;         // 2048 float4 slots
                int row = gg >> 4, s = gg & 15;
                uint32_t dst = sb + (uint32_t)XBUF(q) + (uint32_t)row * 256u
                             + (((uint32_t)s ^ (((uint32_t)row & 7u) << 1)) << 4);
                cp_async16(dst, xf4 + (size_t)(i0 + row) * 64 + q * 16 + s,
                           i0 + row < N_ITEMS_K);
            }
            CP_COMMIT();
        }

        #pragma unroll 1
        for (int q = 0; q < 4; q++) {
            if (q < 3) { CP_WAIT1(); } else { CP_WAIT0(); }
            __syncthreads();
            const int buf = q & 1;

            #pragma unroll
            for (int kq = 0; kq < 4; kq++) {
                // ---- B fragments for this k16 step (all 128 cols) ----
                const int sg = q * 4 + kq;
                const uint32_t bun = ((uint32_t)(2 * sg + b_ku) ^ lane7) << 4;
                uint32_t Bh[8][4], Bl[8][4];
                #pragma unroll
                for (int j = 0; j < 8; j++) {
                    uint32_t bo = b_base + (uint32_t)j * 8192u + bun;
                    ldsm4(Bh[j], sb + SM_WHI + bo);
                    ldsm4(Bl[j], sb + SM_WLO + bo);
                }
                // ---- A fragments: fp32 LDS + in-register hi/lo split ----
                const int kl0 = kq * 16 + 2 * tq;
                float2 v0 = *(const float2*)(sm + xoff(buf, R,     kl0));
                float2 v1 = *(const float2*)(sm + xoff(buf, R + 8, kl0));
                float2 v2 = *(const float2*)(sm + xoff(buf, R,     kl0 + 8));
                float2 v3 = *(const float2*)(sm + xoff(buf, R + 8, kl0 + 8));
                uint32_t Ah[4], Al[4];
                split2(v0.x, v0.y, Ah[0], Al[0]);
                split2(v1.x, v1.y, Ah[1], Al[1]);
                split2(v2.x, v2.y, Ah[2], Al[2]);
                split2(v3.x, v3.y, Ah[3], Al[3]);

                // ---- 3 term passes; acc reuse distance = 16 mmas ----
                #pragma unroll
                for (int j = 0; j < 8; j++) {
                    mma16816(acc[2*j],   Ah, Bh[j][0], Bh[j][1]);
                    mma16816(acc[2*j+1], Ah, Bh[j][2], Bh[j][3]);
                }
                #pragma unroll
                for (int j = 0; j < 8; j++) {
                    mma16816(acc[2*j],   Ah, Bl[j][0], Bl[j][1]);
                    mma16816(acc[2*j+1], Ah, Bl[j][2], Bl[j][3]);
                }
                #pragma unroll
                for (int j = 0; j < 8; j++) {
                    mma16816(acc[2*j],   Al, Bh[j][0], Bh[j][1]);
                    mma16816(acc[2*j+1], Al, Bh[j][2], Bh[j][3]);
                }
            }
            __syncthreads();

            // prefetch quarter q+2 into the buffer just freed
            if (q < 2) {
                #pragma unroll
                for (int it = 0; it < 8; it++) {
                    int gg = it * 256 + tid;
                    int row = gg >> 4, s = gg & 15;
                    uint32_t dst = sb + (uint32_t)XBUF(buf) + (uint32_t)row * 256u
                                 + (((uint32_t)s ^ (((uint32_t)row & 7u) << 1)) << 4);
                    cp_async16(dst, xf4 + (size_t)(i0 + row) * 64 + (q + 2) * 16 + s,
                               i0 + row < N_ITEMS_K);
                }
                CP_COMMIT();
            }
        }

        // ---- epilogue: +b, relu, write h (padded) ----
        {
            const int c0 = tq * 2;
            #pragma unroll
            for (int nt = 0; nt < 16; nt++) {
                const int c = nt * 8 + c0;
                const float b0 = b_s[c], b1 = b_s[c + 1];
                float2 u0, u1;
                u0.x = fmaxf(acc[nt][0] + b0, 0.f);
                u0.y = fmaxf(acc[nt][1] + b1, 0.f);
                u1.x = fmaxf(acc[nt][2] + b0, 0.f);
                u1.y = fmaxf(acc[nt][3] + b1, 0.f);
                *(float2*)&h_s[(size_t)R * H_STRIDE + c]       = u0;
                *(float2*)&h_s[(size_t)(R + 8) * H_STRIDE + c] = u1;
            }
        }
        __syncthreads();

        // ---- segment reduce: 256 threads = 2 row-halves x 128 columns ----
        {
            const int c    = tid & 127;
            const int r0   = (tid >> 7) * 64;
            const int rend = min(rows, r0 + 64);
            if (r0 < rows) {
                float a = 0.f;
                int cur = seg_s[r0];
                for (int r = r0; r < rend; r++) {
                    int s = seg_s[r];
                    if (s != cur) {
                        atomicAdd(&g_scratch[(size_t)cur * BAG_K + c], a);
                        a = 0.f;
                        cur = s;
                    }
                    a += h_s[r * H_STRIDE + c];
                }
                atomicAdd(&g_scratch[(size_t)cur * BAG_K + c], a);
            }
        }
        __syncthreads();
    }
}

// ---- per-column batch stats over the 50k bag means ----
__global__ void __launch_bounds__(128) stats_kernel(const int* __restrict__ blen)
{
    const int c = threadIdx.x;
    float s = 0.f, ss = 0.f;
    for (int r = blockIdx.x; r < N_BAGS_K; r += gridDim.x) {
        float cnt = (float)max(blen[r], 1);
        float v = g_scratch[(size_t)r * BAG_K + c] / cnt;
        s += v;
        ss += v * v;
    }
    atomicAdd(&g_scratch[(size_t)N_BAGS_K * BAG_K + c], s);
    atomicAdd(&g_scratch[(size_t)N_BAGS_K * BAG_K + BAG_K + c], ss);
}

// ---- normalize ----
__global__ void __launch_bounds__(128) norm_kernel(const int* __restrict__ blen,
                                                   const float* __restrict__ gamma,
                                                   const float* __restrict__ beta,
                                                   float* __restrict__ out)
{
    const int c = threadIdx.x;
    const float inv_n = 1.f / (float)N_BAGS_K;
    float mean = g_scratch[(size_t)N_BAGS_K * BAG_K + c] * inv_n;
    float ex2  = g_scratch[(size_t)N_BAGS_K * BAG_K + BAG_K + c] * inv_n;
    float scale = rsqrtf(ex2 - mean * mean + EPS_K) * gamma[c];
    float shift = beta[c];
    for (int r = blockIdx.x; r < N_BAGS_K; r += gridDim.x) {
        float cnt = (float)max(blen[r], 1);
        float v = g_scratch[(size_t)r * BAG_K + c] / cnt;
        out[(size_t)r * BAG_K + c] = (v - mean) * scale + shift;
    }
}

extern "C" void kernel_launch(void* const* d_in, const int* in_sizes, int n_in,
                              void* d_out, int out_size)
{
    const float* x     = (const float*)d_in[0];
    const float* W     = (const float*)d_in[1];
    const float* bvec  = (const float*)d_in[2];
    const float* gamma = (const float*)d_in[3];
    const float* beta  = (const float*)d_in[4];
    const int*   seg   = (const int*)d_in[5];
    const int*   blen  = (const int*)d_in[6];
    float*       out   = (float*)d_out;

    (void)in_sizes; (void)n_in; (void)out_size;

    void* scratch = nullptr;
    cudaGetSymbolAddress(&scratch, g_scratch);
    cudaMemsetAsync(scratch, 0,
                    sizeof(float) * ((size_t)N_BAGS_K * BAG_K + 2 * BAG_K), 0);

    int dev = 0, nsm = 148;
    cudaGetDevice(&dev);
    cudaDeviceGetAttribute(&nsm, cudaDevAttrMultiProcessorCount, dev);

    cudaFuncSetAttribute(fused_gemm_seg_kernel,
                         cudaFuncAttributeMaxDynamicSharedMemorySize, SMEM_DYN);
    fused_gemm_seg_kernel<<<nsm, 256, SMEM_DYN>>>(x, W, bvec, seg);
    stats_kernel<<<500, 128>>>(blen);
    norm_kernel<<<2048, 128>>>(blen, gamma, beta, out);
}

// round 5
// speedup vs baseline: 1.6231x; 1.0126x over previous
#include <cuda_runtime.h>
#include <cuda_fp16.h>
#include <cstdint>

#define N_ITEMS_K 1000000
#define FEAT_K    256
#define BAG_K     128
#define N_BAGS_K  50000
#define TILE_K    128
#define N_TILES_K ((N_ITEMS_K + TILE_K - 1) / TILE_K)   // 7813
#define EPS_K     1e-5f

// ---------------- device scratch ----------------
__device__ float g_scratch[(size_t)N_BAGS_K * BAG_K + 2 * BAG_K];

// ---------------- shared memory layout (byte offsets) ----------------
// seg ids   : [0, 512)
// b vector  : [512, 1024)
// W_hi fp16 : [1024, 66560)      128 rows x 512 B, 16B-unit XOR swizzle
// W_lo fp16 : [66560, 132096)
// x bufs    : [132096, +2x32768) raw fp32 quarters, slot-XOR swizzle
// h (alias) : [132096, +67584)   128 x 132 f32
#define SM_SEG   0
#define SM_B     512
#define SM_WHI   1024
#define SM_WLO   66560
#define SM_X     132096
#define XBUF(b)  (SM_X + (b) * 32768)
#define SM_H     SM_X
#define H_STRIDE 132
#define SMEM_DYN (SM_X + TILE_K * H_STRIDE * 4)   // 199680

__device__ __forceinline__ uint32_t smem_u32(const void* p) {
    uint32_t a;
    asm("{ .reg .u64 t; cvta.to.shared.u64 t, %1; cvt.u32.u64 %0, t; }" : "=r"(a) : "l"(p));
    return a;
}

__device__ __forceinline__ void ldsm4(uint32_t* r, uint32_t addr) {
    asm volatile("ldmatrix.sync.aligned.m8n8.x4.shared.b16 {%0,%1,%2,%3}, [%4];"
                 : "=r"(r[0]), "=r"(r[1]), "=r"(r[2]), "=r"(r[3]) : "r"(addr));
}

__device__ __forceinline__ void mma16816(float* c, const uint32_t* a,
                                         uint32_t b0, uint32_t b1) {
    asm volatile(
        "mma.sync.aligned.m16n8k16.row.col.f32.f16.f16.f32 "
        "{%0,%1,%2,%3},{%4,%5,%6,%7},{%8,%9},{%0,%1,%2,%3};"
        : "+f"(c[0]), "+f"(c[1]), "+f"(c[2]), "+f"(c[3])
        : "r"(a[0]), "r"(a[1]), "r"(a[2]), "r"(a[3]), "r"(b0), "r"(b1));
}

__device__ __forceinline__ void cp_async16(uint32_t dst, const void* src, bool pred) {
    int sz = pred ? 16 : 0;
    asm volatile("cp.async.cg.shared.global [%0], [%1], 16, %2;"
                 :: "r"(dst), "l"(src), "r"(sz) : "memory");
}
#define CP_COMMIT() asm volatile("cp.async.commit_group;" ::: "memory")
#define CP_WAIT1()  asm volatile("cp.async.wait_group 1;" ::: "memory")
#define CP_WAIT0()  asm volatile("cp.async.wait_group 0;" ::: "memory")

__device__ __forceinline__ void split2(float x, float y, uint32_t& hi, uint32_t& lo) {
    __half2 h, l;
    h.x = __float2half_rn(x);
    h.y = __float2half_rn(y);
    l.x = __float2half_rn(x - __half2float(h.x));
    l.y = __float2half_rn(y - __half2float(h.y));
    hi = *(uint32_t*)&h;
    lo = *(uint32_t*)&l;
}

__global__ void __launch_bounds__(512, 1)
fused_gemm_seg_kernel(const float* __restrict__ x, const float* __restrict__ W,
                      const float* __restrict__ bvec, const int* __restrict__ seg)
{
    extern __shared__ char sm[];
    const uint32_t sb = smem_u32(sm);
    const int tid  = threadIdx.x;
    const int lane = tid & 31;
    const int wid  = tid >> 5;

    int*   seg_s = (int*)(sm + SM_SEG);
    float* b_s   = (float*)(sm + SM_B);
    float* h_s   = (float*)(sm + SM_H);

    // ---- one-time: W -> fp16 hi/lo, swizzled [n][512B] ----
    for (int idx = tid; idx < BAG_K * FEAT_K; idx += 512) {
        int n = idx >> 8, k = idx & 255;
        float v = W[idx];
        __half hv = __float2half_rn(v);
        __half lv = __float2half_rn(v - __half2float(hv));
        uint32_t off = (uint32_t)n * 512u
                     + ((uint32_t)((k >> 3) ^ (n & 7)) << 4)
                     + (uint32_t)(k & 7) * 2u;
        *(__half*)(sm + SM_WHI + off) = hv;
        *(__half*)(sm + SM_WLO + off) = lv;
    }
    if (tid < BAG_K) b_s[tid] = bvec[tid];
    __syncthreads();

    // warp tiling: 8 M-groups x 2 N-halves
    const int mgrp  = wid >> 1;          // rows [mgrp*16, +16)
    const int nhalf = wid & 1;           // cols [nhalf*64, +64)

    // fragment lane geometry
    const int g  = lane >> 2;
    const int tq = lane & 3;
    const int b_ln = ((lane >> 4) << 3) + (lane & 7);
    const int b_ku = (lane >> 3) & 1;
    const uint32_t b_base = (uint32_t)(nhalf * 64 + b_ln) * 512u;
    const uint32_t lane7  = (uint32_t)(lane & 7);

    const int R = mgrp * 16 + g;
    const float4* xf4 = (const float4*)x;

    auto xoff = [&](int buf, int r, int kl) -> uint32_t {
        uint32_t s = (uint32_t)(kl >> 2);
        return (uint32_t)XBUF(buf) + (uint32_t)r * 256u
             + ((s ^ (((uint32_t)r & 7u) << 1)) << 4)
             + (uint32_t)(kl & 3) * 4u;
    };

    for (int t = blockIdx.x; t < N_TILES_K; t += gridDim.x) {
        const int i0 = t * TILE_K;
        const int rows = min(TILE_K, N_ITEMS_K - i0);
        if (tid < rows) seg_s[tid] = seg[i0 + tid];

        float acc[8][4];
        #pragma unroll
        for (int nt = 0; nt < 8; nt++)
            #pragma unroll
            for (int i = 0; i < 4; i++) acc[nt][i] = 0.f;

        // ---- prologue: cp.async quarters 0 and 1 ----
        #pragma unroll
        for (int q = 0; q < 2; q++) {
            #pragma unroll
            for (int it = 0; it < 4; it++) {
                int gg = it * 512 + tid;         // 2048 float4 slots
                int row = gg >> 4, s = gg & 15;
                uint32_t dst = sb + (uint32_t)XBUF(q) + (uint32_t)row * 256u
                             + (((uint32_t)s ^ (((uint32_t)row & 7u) << 1)) << 4);
                cp_async16(dst, xf4 + (size_t)(i0 + row) * 64 + q * 16 + s,
                           i0 + row < N_ITEMS_K);
            }
            CP_COMMIT();
        }

        #pragma unroll 1
        for (int q = 0; q < 4; q++) {
            if (q < 3) { CP_WAIT1(); } else { CP_WAIT0(); }
            __syncthreads();
            const int buf = q & 1;

            #pragma unroll
            for (int kq = 0; kq < 4; kq++) {
                // ---- B fragments: only this warp's 64 columns ----
                const int sg = q * 4 + kq;
                const uint32_t bun = ((uint32_t)(2 * sg + b_ku) ^ lane7) << 4;
                uint32_t Bh[4][4], Bl[4][4];
                #pragma unroll
                for (int j = 0; j < 4; j++) {
                    uint32_t bo = b_base + (uint32_t)j * 8192u + bun;
                    ldsm4(Bh[j], sb + SM_WHI + bo);
                    ldsm4(Bl[j], sb + SM_WLO + bo);
                }
                // ---- A fragments: fp32 LDS + in-register hi/lo split ----
                const int kl0 = kq * 16 + 2 * tq;
                float2 v0 = *(const float2*)(sm + xoff(buf, R,     kl0));
                float2 v1 = *(const float2*)(sm + xoff(buf, R + 8, kl0));
                float2 v2 = *(const float2*)(sm + xoff(buf, R,     kl0 + 8));
                float2 v3 = *(const float2*)(sm + xoff(buf, R + 8, kl0 + 8));
                uint32_t Ah[4], Al[4];
                split2(v0.x, v0.y, Ah[0], Al[0]);
                split2(v1.x, v1.y, Ah[1], Al[1]);
                split2(v2.x, v2.y, Ah[2], Al[2]);
                split2(v3.x, v3.y, Ah[3], Al[3]);

                // ---- 3 term passes; acc reuse distance = 8 mmas ----
                #pragma unroll
                for (int j = 0; j < 4; j++) {
                    mma16816(acc[2*j],   Ah, Bh[j][0], Bh[j][1]);
                    mma16816(acc[2*j+1], Ah, Bh[j][2], Bh[j][3]);
                }
                #pragma unroll
                for (int j = 0; j < 4; j++) {
                    mma16816(acc[2*j],   Ah, Bl[j][0], Bl[j][1]);
                    mma16816(acc[2*j+1], Ah, Bl[j][2], Bl[j][3]);
                }
                #pragma unroll
                for (int j = 0; j < 4; j++) {
                    mma16816(acc[2*j],   Al, Bh[j][0], Bh[j][1]);
                    mma16816(acc[2*j+1], Al, Bh[j][2], Bh[j][3]);
                }
            }
            __syncthreads();

            // prefetch quarter q+2 into the freed buffer
            if (q < 2) {
                #pragma unroll
                for (int it = 0; it < 4; it++) {
                    int gg = it * 512 + tid;
                    int row = gg >> 4, s = gg & 15;
                    uint32_t dst = sb + (uint32_t)XBUF(buf) + (uint32_t)row * 256u
                                 + (((uint32_t)s ^ (((uint32_t)row & 7u) << 1)) << 4);
                    cp_async16(dst, xf4 + (size_t)(i0 + row) * 64 + (q + 2) * 16 + s,
                               i0 + row < N_ITEMS_K);
                }
                CP_COMMIT();
            }
        }

        // ---- epilogue: +b, relu, write h (padded) ----
        {
            const int c0 = nhalf * 64 + tq * 2;
            #pragma unroll
            for (int nt = 0; nt < 8; nt++) {
                const int c = c0 + nt * 8;
                const float b0 = b_s[c], b1 = b_s[c + 1];
                float2 u0, u1;
                u0.x = fmaxf(acc[nt][0] + b0, 0.f);
                u0.y = fmaxf(acc[nt][1] + b1, 0.f);
                u1.x = fmaxf(acc[nt][2] + b0, 0.f);
                u1.y = fmaxf(acc[nt][3] + b1, 0.f);
                *(float2*)&h_s[(size_t)R * H_STRIDE + c]       = u0;
                *(float2*)&h_s[(size_t)(R + 8) * H_STRIDE + c] = u1;
            }
        }
        __syncthreads();

        // ---- segment reduce: 512 threads = 4 row-quarters x 128 columns ----
        {
            const int c    = tid & 127;
            const int r0   = (tid >> 7) * 32;
            const int rend = min(rows, r0 + 32);
            if (r0 < rows) {
                float a = 0.f;
                int cur = seg_s[r0];
                for (int r = r0; r < rend; r++) {
                    int s = seg_s[r];
                    if (s != cur) {
                        atomicAdd(&g_scratch[(size_t)cur * BAG_K + c], a);
                        a = 0.f;
                        cur = s;
                    }
                    a += h_s[r * H_STRIDE + c];
                }
                atomicAdd(&g_scratch[(size_t)cur * BAG_K + c], a);
            }
        }
        __syncthreads();
    }
}

// ---- per-column batch stats over the 50k bag means ----
__global__ void __launch_bounds__(128) stats_kernel(const int* __restrict__ blen)
{
    const int c = threadIdx.x;
    float s = 0.f, ss = 0.f;
    for (int r = blockIdx.x; r < N_BAGS_K; r += gridDim.x) {
        float cnt = (float)max(blen[r], 1);
        float v = g_scratch[(size_t)r * BAG_K + c] / cnt;
        s += v;
        ss += v * v;
    }
    atomicAdd(&g_scratch[(size_t)N_BAGS_K * BAG_K + c], s);
    atomicAdd(&g_scratch[(size_t)N_BAGS_K * BAG_K + BAG_K + c], ss);
}

// ---- normalize ----
__global__ void __launch_bounds__(128) norm_kernel(const int* __restrict__ blen,
                                                   const float* __restrict__ gamma,
                                                   const float* __restrict__ beta,
                                                   float* __restrict__ out)
{
    const int c = threadIdx.x;
    const float inv_n = 1.f / (float)N_BAGS_K;
    float mean = g_scratch[(size_t)N_BAGS_K * BAG_K + c] * inv_n;
    float ex2  = g_scratch[(size_t)N_BAGS_K * BAG_K + BAG_K + c] * inv_n;
    float scale = rsqrtf(ex2 - mean * mean + EPS_K) * gamma[c];
    float shift = beta[c];
    for (int r = blockIdx.x; r < N_BAGS_K; r += gridDim.x) {
        float cnt = (float)max(blen[r], 1);
        float v = g_scratch[(size_t)r * BAG_K + c] / cnt;
        out[(size_t)r * BAG_K + c] = (v - mean) * scale + shift;
    }
}

extern "C" void kernel_launch(void* const* d_in, const int* in_sizes, int n_in,
                              void* d_out, int out_size)
{
    const float* x     = (const float*)d_in[0];
    const float* W     = (const float*)d_in[1];
    const float* bvec  = (const float*)d_in[2];
    const float* gamma = (const float*)d_in[3];
    const float* beta  = (const float*)d_in[4];
    const int*   seg   = (const int*)d_in[5];
    const int*   blen  = (const int*)d_in[6];
    float*       out   = (float*)d_out;

    (void)in_sizes; (void)n_in; (void)out_size;

    void* scratch = nullptr;
    cudaGetSymbolAddress(&scratch, g_scratch);
    cudaMemsetAsync(scratch, 0,
                    sizeof(float) * ((size_t)N_BAGS_K * BAG_K + 2 * BAG_K), 0);

    int dev = 0, nsm = 148;
    cudaGetDevice(&dev);
    cudaDeviceGetAttribute(&nsm, cudaDevAttrMultiProcessorCount, dev);

    cudaFuncSetAttribute(fused_gemm_seg_kernel,
                         cudaFuncAttributeMaxDynamicSharedMemorySize, SMEM_DYN);
    fused_gemm_seg_kernel<<<nsm, 512, SMEM_DYN>>>(x, W, bvec, seg);
    stats_kernel<<<500, 128>>>(blen);
    norm_kernel<<<2048, 128>>>(blen, gamma, beta, out);
}

// round 6
// speedup vs baseline: 2.1263x; 1.3100x over previous
#include <cuda_runtime.h>
#include <cuda_fp16.h>
#include <cstdint>

#define N_ITEMS_K 1000000
#define FEAT_K    256
#define BAG_K     128
#define N_BAGS_K  50000
#define TILE_K    64
#define N_TILES_K (N_ITEMS_K / TILE_K)   // 15625 exact
#define EPS_K     1e-5f

// ---------------- device scratch ----------------
__device__ float g_scratch[(size_t)N_BAGS_K * BAG_K + 2 * BAG_K];

// ---------------- shared memory layout (byte offsets) ----------------
// seg ids   : [0, 256)
// b vector  : [512, 1024)
// W_hi fp16 : [1024, 66560)       128 rows x 512 B, 16B-slot XOR swizzle
// x buf 0   : [66560, 132096)     64 rows x 1024 B fp32, slot-XOR swizzle
// x buf 1   : [132096, 197632)
// h         : aliases current x buf (64 x 132 f32 = 33792 B)
#define SM_SEG   0
#define SM_B     512
#define SM_WHI   1024
#define XBUF(b)  (66560 + (b) * 65536)
#define H_STRIDE 132
#define SMEM_DYN 197632

__device__ __forceinline__ uint32_t smem_u32(const void* p) {
    uint32_t a;
    asm("{ .reg .u64 t; cvta.to.shared.u64 t, %1; cvt.u32.u64 %0, t; }" : "=r"(a) : "l"(p));
    return a;
}

__device__ __forceinline__ void ldsm4(uint32_t* r, uint32_t addr) {
    asm volatile("ldmatrix.sync.aligned.m8n8.x4.shared.b16 {%0,%1,%2,%3}, [%4];"
                 : "=r"(r[0]), "=r"(r[1]), "=r"(r[2]), "=r"(r[3]) : "r"(addr));
}

__device__ __forceinline__ void mma16816(float* c, const uint32_t* a,
                                         uint32_t b0, uint32_t b1) {
    asm volatile(
        "mma.sync.aligned.m16n8k16.row.col.f32.f16.f16.f32 "
        "{%0,%1,%2,%3},{%4,%5,%6,%7},{%8,%9},{%0,%1,%2,%3};"
        : "+f"(c[0]), "+f"(c[1]), "+f"(c[2]), "+f"(c[3])
        : "r"(a[0]), "r"(a[1]), "r"(a[2]), "r"(a[3]), "r"(b0), "r"(b1));
}

__device__ __forceinline__ void cp_async16(uint32_t dst, const void* src) {
    asm volatile("cp.async.cg.shared.global [%0], [%1], 16;"
                 :: "r"(dst), "l"(src) : "memory");
}
#define CP_COMMIT() asm volatile("cp.async.commit_group;" ::: "memory")
#define CP_WAIT1()  asm volatile("cp.async.wait_group 1;" ::: "memory")

__device__ __forceinline__ void split2(float x, float y, uint32_t& hi, uint32_t& lo) {
    __half2 h, l;
    h.x = __float2half_rn(x);
    h.y = __float2half_rn(y);
    l.x = __float2half_rn(x - __half2float(h.x));
    l.y = __float2half_rn(y - __half2float(h.y));
    hi = *(uint32_t*)&h;
    lo = *(uint32_t*)&l;
}

// x smem offset for (buf, row, float-index f within 256)
__device__ __forceinline__ uint32_t xoff(int buf, int r, int f) {
    return (uint32_t)XBUF(buf) + (uint32_t)r * 1024u
         + ((((uint32_t)f >> 2) ^ ((uint32_t)r & 7u)) << 4)
         + ((uint32_t)f & 3u) * 4u;
}

__global__ void __launch_bounds__(512, 1)
fused_gemm_seg_kernel(const float* __restrict__ x, const float* __restrict__ W,
                      const float* __restrict__ bvec, const int* __restrict__ seg)
{
    extern __shared__ char sm[];
    const uint32_t sb = smem_u32(sm);
    const int tid  = threadIdx.x;
    const int lane = tid & 31;
    const int wid  = tid >> 5;

    int*   seg_s = (int*)(sm + SM_SEG);
    float* b_s   = (float*)(sm + SM_B);

    // ---- one-time: W -> fp16 (hi only), swizzled [n][512B] ----
    for (int idx = tid; idx < BAG_K * FEAT_K; idx += 512) {
        int n = idx >> 8, k = idx & 255;
        uint32_t off = (uint32_t)n * 512u
                     + ((uint32_t)((k >> 3) ^ (n & 7)) << 4)
                     + (uint32_t)(k & 7) * 2u;
        *(__half*)(sm + SM_WHI + off) = __float2half_rn(W[idx]);
    }
    if (tid < BAG_K) b_s[tid] = bvec[tid];

    // warp tiling: 4 M-groups (16 rows) x 4 N-quarters (32 cols)
    const int mgrp = wid >> 2;
    const int nq   = wid & 3;

    // fragment lane geometry
    const int g  = lane >> 2;
    const int tq = lane & 3;
    const int b_ln = ((lane >> 4) << 3) + (lane & 7);
    const int b_ku = (lane >> 3) & 1;
    const uint32_t b_base = (uint32_t)(nq * 32 + b_ln) * 512u;
    const uint32_t lane7  = (uint32_t)(lane & 7);
    const int R = mgrp * 16 + g;

    const float4* xf4 = (const float4*)x;

    // ---- prologue: prefetch first tile into buf 0 ----
    {
        const int t0 = blockIdx.x;
        #pragma unroll
        for (int it = 0; it < 8; it++) {
            int gg = it * 512 + tid;            // 4096 float4 slots
            int row = gg >> 6, s = gg & 63;
            uint32_t dst = sb + (uint32_t)XBUF(0) + (uint32_t)row * 1024u
                         + ((((uint32_t)s) ^ ((uint32_t)row & 7u)) << 4);
            cp_async16(dst, xf4 + (size_t)(t0 * TILE_K + row) * 64 + s);
        }
        CP_COMMIT();
    }
    __syncthreads();   // W_hi / b ready

    int buf = 0;
    for (int t = blockIdx.x; t < N_TILES_K; t += gridDim.x) {
        // early seg load (used only in reduce; latency hidden by k-loop)
        int segreg = 0;
        if (tid < TILE_K) segreg = seg[t * TILE_K + tid];

        // prefetch next tile into buf^1
        const int tn = t + gridDim.x;
        if (tn < N_TILES_K) {
            #pragma unroll
            for (int it = 0; it < 8; it++) {
                int gg = it * 512 + tid;
                int row = gg >> 6, s = gg & 63;
                uint32_t dst = sb + (uint32_t)XBUF(buf ^ 1) + (uint32_t)row * 1024u
                             + ((((uint32_t)s) ^ ((uint32_t)row & 7u)) << 4);
                cp_async16(dst, xf4 + (size_t)(tn * TILE_K + row) * 64 + s);
            }
        }
        CP_COMMIT();
        CP_WAIT1();        // current tile's data arrived
        __syncthreads();

        float acc[4][4];
        #pragma unroll
        for (int nt = 0; nt < 4; nt++)
            #pragma unroll
            for (int i = 0; i < 4; i++) acc[nt][i] = 0.f;

        // ---- k-loop: 16 k-steps, no syncs, fragment double-buffering ----
        uint32_t Bc[2][4], Bn[2][4];
        float2 vc[4], vn[4];
        {
            const uint32_t bun = ((uint32_t)b_ku ^ lane7) << 4;
            ldsm4(Bc[0], sb + SM_WHI + b_base + bun);
            ldsm4(Bc[1], sb + SM_WHI + b_base + 8192u + bun);
            const int f0 = 2 * tq;
            vc[0] = *(const float2*)(sm + xoff(buf, R,     f0));
            vc[1] = *(const float2*)(sm + xoff(buf, R + 8, f0));
            vc[2] = *(const float2*)(sm + xoff(buf, R,     f0 + 8));
            vc[3] = *(const float2*)(sm + xoff(buf, R + 8, f0 + 8));
        }
        #pragma unroll
        for (int kq = 0; kq < 16; kq++) {
            if (kq < 15) {
                const uint32_t bun = ((uint32_t)(2 * (kq + 1) + b_ku) ^ lane7) << 4;
                ldsm4(Bn[0], sb + SM_WHI + b_base + bun);
                ldsm4(Bn[1], sb + SM_WHI + b_base + 8192u + bun);
                const int f0 = (kq + 1) * 16 + 2 * tq;
                vn[0] = *(const float2*)(sm + xoff(buf, R,     f0));
                vn[1] = *(const float2*)(sm + xoff(buf, R + 8, f0));
                vn[2] = *(const float2*)(sm + xoff(buf, R,     f0 + 8));
                vn[3] = *(const float2*)(sm + xoff(buf, R + 8, f0 + 8));
            }
            uint32_t Ah[4], Al[4];
            split2(vc[0].x, vc[0].y, Ah[0], Al[0]);
            split2(vc[1].x, vc[1].y, Ah[1], Al[1]);
            split2(vc[2].x, vc[2].y, Ah[2], Al[2]);
            split2(vc[3].x, vc[3].y, Ah[3], Al[3]);

            mma16816(acc[0], Ah, Bc[0][0], Bc[0][1]);
            mma16816(acc[1], Ah, Bc[0][2], Bc[0][3]);
            mma16816(acc[2], Ah, Bc[1][0], Bc[1][1]);
            mma16816(acc[3], Ah, Bc[1][2], Bc[1][3]);
            mma16816(acc[0], Al, Bc[0][0], Bc[0][1]);
            mma16816(acc[1], Al, Bc[0][2], Bc[0][3]);
            mma16816(acc[2], Al, Bc[1][0], Bc[1][1]);
            mma16816(acc[3], Al, Bc[1][2], Bc[1][3]);

            #pragma unroll
            for (int j = 0; j < 2; j++)
                #pragma unroll
                for (int i = 0; i < 4; i++) Bc[j][i] = Bn[j][i];
            #pragma unroll
            for (int i = 0; i < 4; i++) vc[i] = vn[i];
        }
        __syncthreads();   // all x reads done before h overwrites this buffer

        // ---- epilogue: +b, relu, write h into consumed x buffer ----
        float* h_s = (float*)(sm + XBUF(buf));
        {
            const int c0 = nq * 32 + 2 * tq;
            #pragma unroll
            for (int nt = 0; nt < 4; nt++) {
                const int c = c0 + nt * 8;
                const float b0 = b_s[c], b1 = b_s[c + 1];
                float2 u0, u1;
                u0.x = fmaxf(acc[nt][0] + b0, 0.f);
                u0.y = fmaxf(acc[nt][1] + b1, 0.f);
                u1.x = fmaxf(acc[nt][2] + b0, 0.f);
                u1.y = fmaxf(acc[nt][3] + b1, 0.f);
                *(float2*)&h_s[(size_t)R * H_STRIDE + c]       = u0;
                *(float2*)&h_s[(size_t)(R + 8) * H_STRIDE + c] = u1;
            }
        }
        if (tid < TILE_K) seg_s[tid] = segreg;
        __syncthreads();

        // ---- segment reduce: 4 row-quarters x 128 columns ----
        {
            const int c  = tid & 127;
            const int r0 = (tid >> 7) * 16;
            float a = 0.f;
            int cur = seg_s[r0];
            #pragma unroll
            for (int r = r0; r < r0 + 16; r++) {
                int s = seg_s[r];
                if (s != cur) {
                    atomicAdd(&g_scratch[(size_t)cur * BAG_K + c], a);
                    a = 0.f;
                    cur = s;
                }
                a += h_s[r * H_STRIDE + c];
            }
            atomicAdd(&g_scratch[(size_t)cur * BAG_K + c], a);
        }
        __syncthreads();   // reduce reads done before next cp.async reuses buffers
        buf ^= 1;
    }
}

// ---- per-column batch stats over the 50k bag means ----
__global__ void __launch_bounds__(128) stats_kernel(const int* __restrict__ blen)
{
    const int c = threadIdx.x;
    float s = 0.f, ss = 0.f;
    for (int r = blockIdx.x; r < N_BAGS_K; r += gridDim.x) {
        float cnt = (float)max(blen[r], 1);
        float v = g_scratch[(size_t)r * BAG_K + c] / cnt;
        s += v;
        ss += v * v;
    }
    atomicAdd(&g_scratch[(size_t)N_BAGS_K * BAG_K + c], s);
    atomicAdd(&g_scratch[(size_t)N_BAGS_K * BAG_K + BAG_K + c], ss);
}

// ---- normalize ----
__global__ void __launch_bounds__(128) norm_kernel(const int* __restrict__ blen,
                                                   const float* __restrict__ gamma,
                                                   const float* __restrict__ beta,
                                                   float* __restrict__ out)
{
    const int c = threadIdx.x;
    const float inv_n = 1.f / (float)N_BAGS_K;
    float mean = g_scratch[(size_t)N_BAGS_K * BAG_K + c] * inv_n;
    float ex2  = g_scratch[(size_t)N_BAGS_K * BAG_K + BAG_K + c] * inv_n;
    float scale = rsqrtf(ex2 - mean * mean + EPS_K) * gamma[c];
    float shift = beta[c];
    for (int r = blockIdx.x; r < N_BAGS_K; r += gridDim.x) {
        float cnt = (float)max(blen[r], 1);
        float v = g_scratch[(size_t)r * BAG_K + c] / cnt;
        out[(size_t)r * BAG_K + c] = (v - mean) * scale + shift;
    }
}

extern "C" void kernel_launch(void* const* d_in, const int* in_sizes, int n_in,
                              void* d_out, int out_size)
{
    const float* x     = (const float*)d_in[0];
    const float* W     = (const float*)d_in[1];
    const float* bvec  = (const float*)d_in[2];
    const float* gamma = (const float*)d_in[3];
    const float* beta  = (const float*)d_in[4];
    const int*   seg   = (const int*)d_in[5];
    const int*   blen  = (const int*)d_in[6];
    float*       out   = (float*)d_out;

    (void)in_sizes; (void)n_in; (void)out_size;

    void* scratch = nullptr;
    cudaGetSymbolAddress(&scratch, g_scratch);
    cudaMemsetAsync(scratch, 0,
                    sizeof(float) * ((size_t)N_BAGS_K * BAG_K + 2 * BAG_K), 0);

    int dev = 0, nsm = 148;
    cudaGetDevice(&dev);
    cudaDeviceGetAttribute(&nsm, cudaDevAttrMultiProcessorCount, dev);

    cudaFuncSetAttribute(fused_gemm_seg_kernel,
                         cudaFuncAttributeMaxDynamicSharedMemorySize, SMEM_DYN);
    fused_gemm_seg_kernel<<<nsm, 512, SMEM_DYN>>>(x, W, bvec, seg);
    stats_kernel<<<1024, 128>>>(blen);
    norm_kernel<<<2048, 128>>>(blen, gamma, beta, out);
}